// round 1
// baseline (speedup 1.0000x reference)
#include <cuda_runtime.h>
#include <math.h>

#define Bb 4
#define Ss 2048
#define Dd 2048
#define Hh 16
#define HDim 128
#define MROWS (Bb * Ss)  // 8192

// Scratch (allocation-free: device globals)
__device__ float g_Q[(size_t)Bb * Ss * Dd];
__device__ float g_K[(size_t)Bb * Ss * Dd];
__device__ float g_V[(size_t)Bb * Ss * Dd];
__device__ float g_C[(size_t)Bb * Ss * Dd];
__device__ float g_tab[Ss * 64 * 2];  // cos/sin table [s][j][2]

// ---------------------------------------------------------------------------
// Tiled fp32 GEMM + bias: C[M,N] = A[M,K] @ W[K,N] + bias[N]
// BM=BN=128, BK=8, 256 threads, 8x8 per thread.
// ---------------------------------------------------------------------------
__global__ __launch_bounds__(256) void gemm_bias_kernel(
    const float* __restrict__ A, const float* __restrict__ W,
    const float* __restrict__ bias, float* __restrict__ C,
    int M, int N, int K)
{
    __shared__ float As[8][132];   // [k][row], padded
    __shared__ float Bs[8][128];   // [k][col]

    const int tid = threadIdx.x;
    const int tx = tid & 15;       // col group 0..15
    const int ty = tid >> 4;       // row group 0..15
    const int rowBase = blockIdx.y * 128;
    const int colBase = blockIdx.x * 128;

    const int aRow = tid >> 1;          // 0..127
    const int aCol = (tid & 1) * 4;     // 0 or 4
    const int bRow = tid >> 5;          // 0..7
    const int bCol = (tid & 31) * 4;    // 0..124

    const float* Aptr = A + (size_t)(rowBase + aRow) * K + aCol;
    const float* Wptr = W + (size_t)bRow * N + colBase + bCol;

    float acc[8][8];
    #pragma unroll
    for (int i = 0; i < 8; i++)
        #pragma unroll
        for (int j = 0; j < 8; j++) acc[i][j] = 0.f;

    for (int kt = 0; kt < K; kt += 8) {
        float4 a4 = *(const float4*)(Aptr + kt);
        float4 b4 = *(const float4*)(Wptr + (size_t)kt * N);
        As[aCol + 0][aRow] = a4.x;
        As[aCol + 1][aRow] = a4.y;
        As[aCol + 2][aRow] = a4.z;
        As[aCol + 3][aRow] = a4.w;
        *(float4*)&Bs[bRow][bCol] = b4;
        __syncthreads();

        #pragma unroll
        for (int k = 0; k < 8; k++) {
            float4 a0 = *(const float4*)&As[k][ty * 8];
            float4 a1 = *(const float4*)&As[k][ty * 8 + 4];
            float4 b0 = *(const float4*)&Bs[k][tx * 8];
            float4 b1 = *(const float4*)&Bs[k][tx * 8 + 4];
            float ar[8] = {a0.x, a0.y, a0.z, a0.w, a1.x, a1.y, a1.z, a1.w};
            float br[8] = {b0.x, b0.y, b0.z, b0.w, b1.x, b1.y, b1.z, b1.w};
            #pragma unroll
            for (int i = 0; i < 8; i++)
                #pragma unroll
                for (int j = 0; j < 8; j++)
                    acc[i][j] += ar[i] * br[j];
        }
        __syncthreads();
    }

    float4 bb0 = *(const float4*)(bias + colBase + tx * 8);
    float4 bb1 = *(const float4*)(bias + colBase + tx * 8 + 4);
    #pragma unroll
    for (int i = 0; i < 8; i++) {
        size_t row = (size_t)(rowBase + ty * 8 + i);
        float* Crow = C + row * N + colBase + tx * 8;
        float4 o0 = make_float4(acc[i][0] + bb0.x, acc[i][1] + bb0.y,
                                acc[i][2] + bb0.z, acc[i][3] + bb0.w);
        float4 o1 = make_float4(acc[i][4] + bb1.x, acc[i][5] + bb1.y,
                                acc[i][6] + bb1.z, acc[i][7] + bb1.w);
        *(float4*)Crow = o0;
        *(float4*)(Crow + 4) = o1;
    }
}

// ---------------------------------------------------------------------------
// RoPE cos/sin table in double precision (angle up to ~2047 rad: fast-math
// relative error on f would produce >1e-3 absolute angle error; fp64 avoids it)
// ---------------------------------------------------------------------------
__global__ void rope_table_kernel(const float* __restrict__ base_p)
{
    int t = blockIdx.x * blockDim.x + threadIdx.x;
    if (t >= Ss * 64) return;
    int s = t >> 6, j = t & 63;
    double base = (double)(*base_p);
    double f = pow(base, -(double)j / 64.0);
    double ang = (double)s * f;
    g_tab[2 * t]     = (float)cos(ang);
    g_tab[2 * t + 1] = (float)sin(ang);
}

// ---------------------------------------------------------------------------
// RoPE apply in-place. One thread per (even,odd) pair.
// Layout: row = (b*S+s), within row: pair p in 0..1023, j = p & 63.
// ---------------------------------------------------------------------------
__global__ __launch_bounds__(256) void rope_apply_kernel(float* __restrict__ x)
{
    int idx = blockIdx.x * blockDim.x + threadIdx.x;  // < B*S*D/2
    int p = idx & 1023;
    int j = p & 63;
    int s = (idx >> 10) & (Ss - 1);
    float2 v = ((float2*)x)[idx];
    float c  = g_tab[2 * (s * 64 + j)];
    float sn = g_tab[2 * (s * 64 + j) + 1];
    float2 o;
    o.x = v.x * c - v.y * sn;
    o.y = v.x * sn + v.y * c;
    ((float2*)x)[idx] = o;
}

// ---------------------------------------------------------------------------
// Flash attention (fp32, causal, online softmax).
// Block: one (b, h, 64-row q tile). 256 threads.
// Each thread: 4 score rows (ty*4+i) x 4 score cols (tx + 16*j),
// and output tile 4 rows x 8 cols (tx*8..tx*8+7).
// smem: sQ/sK/sV [64][132], sS [64][68].
// ---------------------------------------------------------------------------
#define QSTRIDE 132
#define SSTRIDE 68
#define FLASH_SMEM ((3 * 64 * QSTRIDE + 64 * SSTRIDE) * 4)

__global__ __launch_bounds__(256) void flash_kernel(
    const float* __restrict__ Q, const float* __restrict__ K,
    const float* __restrict__ V, float* __restrict__ O)
{
    extern __shared__ float sm[];
    float* sQ = sm;
    float* sK = sm + 64 * QSTRIDE;
    float* sV = sm + 2 * 64 * QSTRIDE;
    float* sS = sm + 3 * 64 * QSTRIDE;

    const int qt = blockIdx.x, h = blockIdx.y, b = blockIdx.z;
    const int tid = threadIdx.x;
    const int tx = tid & 15, ty = tid >> 4;
    const int r0 = ty * 4;
    const int q0 = qt * 64;
    const float scale = 0.08838834764831845f;  // 1/sqrt(128)

    const float* Qg = Q + ((size_t)(b * Ss + q0)) * Dd + h * HDim;
    {
        int lr = tid >> 5;
        int lc = (tid & 31) << 2;
        #pragma unroll
        for (int i = 0; i < 8; i++) {
            float4 v = *(const float4*)(Qg + (size_t)(lr + i * 8) * Dd + lc);
            *(float4*)&sQ[(lr + i * 8) * QSTRIDE + lc] = v;
        }
    }

    float m[4], l[4], o[4][8];
    #pragma unroll
    for (int i = 0; i < 4; i++) {
        m[i] = -1e30f; l[i] = 0.f;
        #pragma unroll
        for (int j = 0; j < 8; j++) o[i][j] = 0.f;
    }

    for (int kt = 0; kt <= qt; ++kt) {
        const int k0 = kt * 64;
        const float* Kg = K + ((size_t)(b * Ss + k0)) * Dd + h * HDim;
        const float* Vg = V + ((size_t)(b * Ss + k0)) * Dd + h * HDim;
        __syncthreads();  // previous-iter consumers done before overwrite
        {
            int lr = tid >> 5;
            int lc = (tid & 31) << 2;
            #pragma unroll
            for (int i = 0; i < 8; i++) {
                *(float4*)&sK[(lr + i * 8) * QSTRIDE + lc] =
                    *(const float4*)(Kg + (size_t)(lr + i * 8) * Dd + lc);
                *(float4*)&sV[(lr + i * 8) * QSTRIDE + lc] =
                    *(const float4*)(Vg + (size_t)(lr + i * 8) * Dd + lc);
            }
        }
        __syncthreads();

        // scores: 4 rows x 4 strided cols
        float acc[4][4];
        #pragma unroll
        for (int i = 0; i < 4; i++)
            #pragma unroll
            for (int j = 0; j < 4; j++) acc[i][j] = 0.f;

        #pragma unroll 4
        for (int d = 0; d < 128; d += 4) {
            float4 qv[4], kv[4];
            #pragma unroll
            for (int i = 0; i < 4; i++)
                qv[i] = *(const float4*)&sQ[(r0 + i) * QSTRIDE + d];
            #pragma unroll
            for (int j = 0; j < 4; j++)
                kv[j] = *(const float4*)&sK[(tx + 16 * j) * QSTRIDE + d];
            #pragma unroll
            for (int i = 0; i < 4; i++)
                #pragma unroll
                for (int j = 0; j < 4; j++)
                    acc[i][j] += qv[i].x * kv[j].x + qv[i].y * kv[j].y +
                                 qv[i].z * kv[j].z + qv[i].w * kv[j].w;
        }

        const bool diag = (kt == qt);
        #pragma unroll
        for (int i = 0; i < 4; i++) {
            float mt = -1e30f;
            #pragma unroll
            for (int j = 0; j < 4; j++) {
                float s = acc[i][j] * scale;
                if (diag && (tx + 16 * j) > (r0 + i)) s = -1e30f;
                acc[i][j] = s;
                mt = fmaxf(mt, s);
            }
            #pragma unroll
            for (int off = 8; off > 0; off >>= 1)
                mt = fmaxf(mt, __shfl_xor_sync(0xffffffffu, mt, off));
            float mnew = fmaxf(m[i], mt);
            float alpha = __expf(m[i] - mnew);
            float rs = 0.f;
            #pragma unroll
            for (int j = 0; j < 4; j++) {
                float pv = __expf(acc[i][j] - mnew);
                sS[(r0 + i) * SSTRIDE + tx + 16 * j] = pv;
                rs += pv;
            }
            #pragma unroll
            for (int off = 8; off > 0; off >>= 1)
                rs += __shfl_xor_sync(0xffffffffu, rs, off);
            l[i] = l[i] * alpha + rs;
            m[i] = mnew;
            #pragma unroll
            for (int j = 0; j < 8; j++) o[i][j] *= alpha;
        }
        __syncwarp();  // sS produced/consumed within the same warp's ty group

        // O += P @ V
        #pragma unroll 2
        for (int t = 0; t < 64; t++) {
            float4 v0 = *(const float4*)&sV[t * QSTRIDE + tx * 8];
            float4 v1 = *(const float4*)&sV[t * QSTRIDE + tx * 8 + 4];
            #pragma unroll
            for (int i = 0; i < 4; i++) {
                float pv = sS[(r0 + i) * SSTRIDE + t];
                o[i][0] += pv * v0.x; o[i][1] += pv * v0.y;
                o[i][2] += pv * v0.z; o[i][3] += pv * v0.w;
                o[i][4] += pv * v1.x; o[i][5] += pv * v1.y;
                o[i][6] += pv * v1.z; o[i][7] += pv * v1.w;
            }
        }
    }

    float* Og = O + ((size_t)(b * Ss + q0)) * Dd + h * HDim;
    #pragma unroll
    for (int i = 0; i < 4; i++) {
        float inv = 1.f / l[i];
        float4 w0 = make_float4(o[i][0] * inv, o[i][1] * inv,
                                o[i][2] * inv, o[i][3] * inv);
        float4 w1 = make_float4(o[i][4] * inv, o[i][5] * inv,
                                o[i][6] * inv, o[i][7] * inv);
        *(float4*)(Og + (size_t)(r0 + i) * Dd + tx * 8) = w0;
        *(float4*)(Og + (size_t)(r0 + i) * Dd + tx * 8 + 4) = w1;
    }
}

// ---------------------------------------------------------------------------
extern "C" void kernel_launch(void* const* d_in, const int* in_sizes, int n_in,
                              void* d_out, int out_size)
{
    const float* subj = (const float*)d_in[0];
    const float* obj  = (const float*)d_in[1];
    const float* wq   = (const float*)d_in[2];
    const float* bq   = (const float*)d_in[3];
    const float* wk   = (const float*)d_in[4];
    const float* bk   = (const float*)d_in[5];
    const float* wv   = (const float*)d_in[6];
    const float* bv   = (const float*)d_in[7];
    const float* wc   = (const float*)d_in[8];
    const float* bc   = (const float*)d_in[9];
    const float* base = (const float*)d_in[10];
    float* out = (float*)d_out;

    float *Q, *K, *V, *C;
    cudaGetSymbolAddress((void**)&Q, g_Q);
    cudaGetSymbolAddress((void**)&K, g_K);
    cudaGetSymbolAddress((void**)&V, g_V);
    cudaGetSymbolAddress((void**)&C, g_C);

    cudaFuncSetAttribute(flash_kernel,
                         cudaFuncAttributeMaxDynamicSharedMemorySize, FLASH_SMEM);

    dim3 gg(Dd / 128, MROWS / 128);
    gemm_bias_kernel<<<gg, 256>>>(subj, wq, bq, Q, MROWS, Dd, Dd);
    gemm_bias_kernel<<<gg, 256>>>(obj,  wk, bk, K, MROWS, Dd, Dd);
    gemm_bias_kernel<<<gg, 256>>>(obj,  wv, bv, V, MROWS, Dd, Dd);

    rope_table_kernel<<<(Ss * 64 + 255) / 256, 256>>>(base);
    int npairs = Bb * Ss * Dd / 2;
    rope_apply_kernel<<<npairs / 256, 256>>>(Q);
    rope_apply_kernel<<<npairs / 256, 256>>>(K);

    flash_kernel<<<dim3(Ss / 64, Hh, Bb), 256, FLASH_SMEM>>>(Q, K, V, C);

    gemm_bias_kernel<<<gg, 256>>>(C, wc, bc, out, MROWS, Dd, Dd);
}

// round 6
// speedup vs baseline: 2.1912x; 2.1912x over previous
#include <cuda_runtime.h>
#include <math.h>
#include <stdint.h>

#define Bb 4
#define Ss 2048
#define Dd 2048
#define Hh 16
#define HDim 128
#define MROWS (Bb * Ss)  // 8192

// Scratch (allocation-free: device globals)
__device__ float g_Q[(size_t)Bb * Ss * Dd];
__device__ float g_K[(size_t)Bb * Ss * Dd];
__device__ float g_V[(size_t)Bb * Ss * Dd];
__device__ float g_C[(size_t)Bb * Ss * Dd];
__device__ float2 g_tab2[64 * Ss];   // [j][s] -> (cos, sin)

// ---------------------------------------------------------------------------
// helpers
// ---------------------------------------------------------------------------
__device__ __forceinline__ uint32_t smem_u32(const void* p) {
    uint32_t r;
    asm("{ .reg .u64 t; cvta.to.shared.u64 t, %1; cvt.u32.u64 %0, t; }"
        : "=r"(r) : "l"(p));
    return r;
}

#define CP_ASYNC16(smem, gptr) \
    asm volatile("cp.async.cg.shared.global [%0], [%1], 16;" \
                 :: "r"(smem), "l"(gptr) : "memory")
#define CP_COMMIT() asm volatile("cp.async.commit_group;" ::: "memory")
#define CP_WAIT(n)  asm volatile("cp.async.wait_group %0;" :: "n"(n) : "memory")

__device__ __forceinline__ uint32_t cvt_tf32(float x) {
    uint32_t r;
    asm("cvt.rna.tf32.f32 %0, %1;" : "=r"(r) : "f"(x));
    return r;
}

__device__ __forceinline__ void mma_m16n8k8(float* d, const uint32_t* a,
                                            uint32_t b0, uint32_t b1) {
    asm volatile(
        "mma.sync.aligned.m16n8k8.row.col.f32.tf32.tf32.f32 "
        "{%0,%1,%2,%3}, {%4,%5,%6,%7}, {%8,%9}, {%0,%1,%2,%3};"
        : "+f"(d[0]), "+f"(d[1]), "+f"(d[2]), "+f"(d[3])
        : "r"(a[0]), "r"(a[1]), "r"(a[2]), "r"(a[3]), "r"(b0), "r"(b1));
}

// ---------------------------------------------------------------------------
// tf32 mma.sync GEMM: C[8192,2048] = A[8192,2048] @ W[2048,2048] + bias
// W in original [K,N] layout. Optional fused RoPE (bias first, then rotate).
// BM=BN=128, BK=32, 2-stage cp.async pipeline, 256 threads, 2 CTAs/SM.
// ---------------------------------------------------------------------------
#define BKt 32
#define NKT (Dd / BKt)            // 64
#define SA_STRIDE 36              // words; fragment LDS conflict-free
#define SB_STRIDE 136             // words; fragment LDS conflict-free
#define SA_WORDS (128 * SA_STRIDE)   // 4608
#define SB_WORDS (BKt * SB_STRIDE)   // 4352
#define STAGE_WORDS (SA_WORDS + SB_WORDS)
#define GEMM_SMEM (2 * STAGE_WORDS * 4)  // 71680 B

__global__ __launch_bounds__(256, 2) void gemm_tc_kernel(
    const float* __restrict__ A, const float* __restrict__ W,
    const float* __restrict__ bias, float* __restrict__ C, int doRope)
{
    extern __shared__ float sm[];
    const int tid = threadIdx.x;
    const int wid = tid >> 5;
    const int lane = tid & 31;
    const int rowBase = blockIdx.y * 128;
    const int colBase = blockIdx.x * 128;

    const uint32_t sbase = smem_u32(sm);

    // global load mapping
    // A tile: 128 rows x 32 cols; thread -> row tid>>3 (+32i), f4col tid&7
    // B tile: 32 rows x 128 cols; thread -> row tid>>5 (+8i),  f4col tid&31
    const float* aG = A + (size_t)(rowBase + (tid >> 3)) * Dd + (tid & 7) * 4;
    const float* bG = W + (size_t)(tid >> 5) * Dd + colBase + (tid & 31) * 4;
    const uint32_t aS = sbase + ((tid >> 3) * SA_STRIDE + (tid & 7) * 4) * 4;
    const uint32_t bS = sbase + (SA_WORDS + (tid >> 5) * SB_STRIDE + (tid & 31) * 4) * 4;

    const int wr = wid & 3;       // warp row group (32 rows)
    const int wc = wid >> 2;      // warp col group (64 cols)
    const int m0 = wr * 32;
    const int n0 = wc * 64;
    const int lg = lane >> 2;     // 0..7
    const int lc = lane & 3;      // 0..3

    float acc[2][8][4];
    #pragma unroll
    for (int mi = 0; mi < 2; mi++)
        #pragma unroll
        for (int ni = 0; ni < 8; ni++)
            #pragma unroll
            for (int r = 0; r < 4; r++) acc[mi][ni][r] = 0.f;

    // prologue: stage 0
    {
        const float* ag = aG;
        const float* bg = bG;
        #pragma unroll
        for (int i = 0; i < 4; i++) {
            CP_ASYNC16(aS + i * 32 * SA_STRIDE * 4, ag + (size_t)(32 * i) * Dd);
            CP_ASYNC16(bS + i * 8 * SB_STRIDE * 4,  bg + (size_t)(8 * i) * Dd);
        }
        CP_COMMIT();
    }

    for (int kt = 0; kt < NKT; kt++) {
        const int s = kt & 1;
        if (kt + 1 < NKT) {
            const int s2 = (kt + 1) & 1;
            const float* ag = aG + (kt + 1) * BKt;
            const float* bg = bG + (size_t)(kt + 1) * BKt * Dd;
            const uint32_t as = aS + s2 * STAGE_WORDS * 4;
            const uint32_t bs = bS + s2 * STAGE_WORDS * 4;
            #pragma unroll
            for (int i = 0; i < 4; i++) {
                CP_ASYNC16(as + i * 32 * SA_STRIDE * 4, ag + (size_t)(32 * i) * Dd);
                CP_ASYNC16(bs + i * 8 * SB_STRIDE * 4,  bg + (size_t)(8 * i) * Dd);
            }
            CP_COMMIT();
            CP_WAIT(1);
        } else {
            CP_WAIT(0);
        }
        __syncthreads();

        const float* sAp = sm + s * STAGE_WORDS;
        const float* sBp = sAp + SA_WORDS;

        #pragma unroll
        for (int ks = 0; ks < 4; ks++) {
            const int k0 = ks * 8;
            uint32_t afr[2][4];
            #pragma unroll
            for (int mi = 0; mi < 2; mi++) {
                const int r = m0 + mi * 16 + lg;
                const int c = k0 + lc;
                afr[mi][0] = cvt_tf32(sAp[r * SA_STRIDE + c]);
                afr[mi][1] = cvt_tf32(sAp[(r + 8) * SA_STRIDE + c]);
                afr[mi][2] = cvt_tf32(sAp[r * SA_STRIDE + c + 4]);
                afr[mi][3] = cvt_tf32(sAp[(r + 8) * SA_STRIDE + c + 4]);
            }
            #pragma unroll
            for (int ni = 0; ni < 8; ni++) {
                const int col = n0 + ni * 8 + lg;
                uint32_t b0 = cvt_tf32(sBp[(k0 + lc) * SB_STRIDE + col]);
                uint32_t b1 = cvt_tf32(sBp[(k0 + 4 + lc) * SB_STRIDE + col]);
                mma_m16n8k8(acc[0][ni], afr[0], b0, b1);
                mma_m16n8k8(acc[1][ni], afr[1], b0, b1);
            }
        }
        __syncthreads();
    }

    // Epilogue: bias then optional RoPE; c-frag (c0,c1) is an (even,odd) pair.
    #pragma unroll
    for (int mi = 0; mi < 2; mi++) {
        const int row = rowBase + m0 + mi * 16 + lg;
        #pragma unroll
        for (int ni = 0; ni < 8; ni++) {
            const int col = colBase + n0 + ni * 8 + 2 * lc;
            const float bv0 = __ldg(bias + col);
            const float bv1 = __ldg(bias + col + 1);
            const int jn = (col & 127) >> 1;

            #pragma unroll
            for (int half = 0; half < 2; half++) {
                const int r = row + half * 8;
                float x0 = acc[mi][ni][2 * half]     + bv0;
                float x1 = acc[mi][ni][2 * half + 1] + bv1;
                if (doRope) {
                    float2 cs = g_tab2[jn * Ss + (r & (Ss - 1))];
                    float y0 = x0 * cs.x - x1 * cs.y;
                    float y1 = x0 * cs.y + x1 * cs.x;
                    x0 = y0; x1 = y1;
                }
                *(float2*)(C + (size_t)r * Dd + col) = make_float2(x0, x1);
            }
        }
    }
}

// ---------------------------------------------------------------------------
// RoPE cos/sin table (fp64 for angle accuracy), layout [j][s]
// ---------------------------------------------------------------------------
__global__ void rope_table2_kernel(const float* __restrict__ base_p)
{
    int t = blockIdx.x * blockDim.x + threadIdx.x;
    if (t >= 64 * Ss) return;
    int j = t >> 11, s = t & (Ss - 1);
    double base = (double)(*base_p);
    double f = exp(-(double)j / 64.0 * log(base));
    double ang = (double)s * f;
    double sn, cs;
    sincos(ang, &sn, &cs);
    g_tab2[t] = make_float2((float)cs, (float)sn);
}

// ---------------------------------------------------------------------------
// Flash attention (fp32, causal, online softmax) — R1 kernel, known good.
// ---------------------------------------------------------------------------
#define QSTRIDE 132
#define SSTRIDE 68
#define FLASH_SMEM ((3 * 64 * QSTRIDE + 64 * SSTRIDE) * 4)

__global__ __launch_bounds__(256) void flash_kernel(
    const float* __restrict__ Q, const float* __restrict__ K,
    const float* __restrict__ V, float* __restrict__ O)
{
    extern __shared__ float smf[];
    float* sQ = smf;
    float* sK = smf + 64 * QSTRIDE;
    float* sV = smf + 2 * 64 * QSTRIDE;
    float* sS = smf + 3 * 64 * QSTRIDE;

    const int qt = blockIdx.x, h = blockIdx.y, b = blockIdx.z;
    const int tid = threadIdx.x;
    const int tx = tid & 15, ty = tid >> 4;
    const int r0 = ty * 4;
    const int q0 = qt * 64;
    const float scale = 0.08838834764831845f;

    const float* Qg = Q + ((size_t)(b * Ss + q0)) * Dd + h * HDim;
    {
        int lr = tid >> 5;
        int lc = (tid & 31) << 2;
        #pragma unroll
        for (int i = 0; i < 8; i++) {
            float4 v = *(const float4*)(Qg + (size_t)(lr + i * 8) * Dd + lc);
            *(float4*)&sQ[(lr + i * 8) * QSTRIDE + lc] = v;
        }
    }

    float m[4], l[4], o[4][8];
    #pragma unroll
    for (int i = 0; i < 4; i++) {
        m[i] = -1e30f; l[i] = 0.f;
        #pragma unroll
        for (int j = 0; j < 8; j++) o[i][j] = 0.f;
    }

    for (int kt = 0; kt <= qt; ++kt) {
        const int k0 = kt * 64;
        const float* Kg = K + ((size_t)(b * Ss + k0)) * Dd + h * HDim;
        const float* Vg = V + ((size_t)(b * Ss + k0)) * Dd + h * HDim;
        __syncthreads();
        {
            int lr = tid >> 5;
            int lc = (tid & 31) << 2;
            #pragma unroll
            for (int i = 0; i < 8; i++) {
                *(float4*)&sK[(lr + i * 8) * QSTRIDE + lc] =
                    *(const float4*)(Kg + (size_t)(lr + i * 8) * Dd + lc);
                *(float4*)&sV[(lr + i * 8) * QSTRIDE + lc] =
                    *(const float4*)(Vg + (size_t)(lr + i * 8) * Dd + lc);
            }
        }
        __syncthreads();

        float acc[4][4];
        #pragma unroll
        for (int i = 0; i < 4; i++)
            #pragma unroll
            for (int j = 0; j < 4; j++) acc[i][j] = 0.f;

        #pragma unroll 4
        for (int d = 0; d < 128; d += 4) {
            float4 qv[4], kv[4];
            #pragma unroll
            for (int i = 0; i < 4; i++)
                qv[i] = *(const float4*)&sQ[(r0 + i) * QSTRIDE + d];
            #pragma unroll
            for (int j = 0; j < 4; j++)
                kv[j] = *(const float4*)&sK[(tx + 16 * j) * QSTRIDE + d];
            #pragma unroll
            for (int i = 0; i < 4; i++)
                #pragma unroll
                for (int j = 0; j < 4; j++)
                    acc[i][j] += qv[i].x * kv[j].x + qv[i].y * kv[j].y +
                                 qv[i].z * kv[j].z + qv[i].w * kv[j].w;
        }

        const bool diag = (kt == qt);
        #pragma unroll
        for (int i = 0; i < 4; i++) {
            float mt = -1e30f;
            #pragma unroll
            for (int j = 0; j < 4; j++) {
                float s = acc[i][j] * scale;
                if (diag && (tx + 16 * j) > (r0 + i)) s = -1e30f;
                acc[i][j] = s;
                mt = fmaxf(mt, s);
            }
            #pragma unroll
            for (int off = 8; off > 0; off >>= 1)
                mt = fmaxf(mt, __shfl_xor_sync(0xffffffffu, mt, off));
            float mnew = fmaxf(m[i], mt);
            float alpha = __expf(m[i] - mnew);
            float rs = 0.f;
            #pragma unroll
            for (int j = 0; j < 4; j++) {
                float pv = __expf(acc[i][j] - mnew);
                sS[(r0 + i) * SSTRIDE + tx + 16 * j] = pv;
                rs += pv;
            }
            #pragma unroll
            for (int off = 8; off > 0; off >>= 1)
                rs += __shfl_xor_sync(0xffffffffu, rs, off);
            l[i] = l[i] * alpha + rs;
            m[i] = mnew;
            #pragma unroll
            for (int j = 0; j < 8; j++) o[i][j] *= alpha;
        }
        __syncwarp();

        #pragma unroll 2
        for (int t = 0; t < 64; t++) {
            float4 v0 = *(const float4*)&sV[t * QSTRIDE + tx * 8];
            float4 v1 = *(const float4*)&sV[t * QSTRIDE + tx * 8 + 4];
            #pragma unroll
            for (int i = 0; i < 4; i++) {
                float pv = sS[(r0 + i) * SSTRIDE + t];
                o[i][0] += pv * v0.x; o[i][1] += pv * v0.y;
                o[i][2] += pv * v0.z; o[i][3] += pv * v0.w;
                o[i][4] += pv * v1.x; o[i][5] += pv * v1.y;
                o[i][6] += pv * v1.z; o[i][7] += pv * v1.w;
            }
        }
    }

    float* Og = O + ((size_t)(b * Ss + q0)) * Dd + h * HDim;
    #pragma unroll
    for (int i = 0; i < 4; i++) {
        float inv = 1.f / l[i];
        float4 w0 = make_float4(o[i][0] * inv, o[i][1] * inv,
                                o[i][2] * inv, o[i][3] * inv);
        float4 w1 = make_float4(o[i][4] * inv, o[i][5] * inv,
                                o[i][6] * inv, o[i][7] * inv);
        *(float4*)(Og + (size_t)(r0 + i) * Dd + tx * 8) = w0;
        *(float4*)(Og + (size_t)(r0 + i) * Dd + tx * 8 + 4) = w1;
    }
}

// ---------------------------------------------------------------------------
extern "C" void kernel_launch(void* const* d_in, const int* in_sizes, int n_in,
                              void* d_out, int out_size)
{
    const float* subj = (const float*)d_in[0];
    const float* obj  = (const float*)d_in[1];
    const float* wq   = (const float*)d_in[2];
    const float* bq   = (const float*)d_in[3];
    const float* wk   = (const float*)d_in[4];
    const float* bk   = (const float*)d_in[5];
    const float* wv   = (const float*)d_in[6];
    const float* bv   = (const float*)d_in[7];
    const float* wc   = (const float*)d_in[8];
    const float* bc   = (const float*)d_in[9];
    const float* base = (const float*)d_in[10];
    float* out = (float*)d_out;

    float *Q, *K, *V, *C;
    cudaGetSymbolAddress((void**)&Q, g_Q);
    cudaGetSymbolAddress((void**)&K, g_K);
    cudaGetSymbolAddress((void**)&V, g_V);
    cudaGetSymbolAddress((void**)&C, g_C);

    cudaFuncSetAttribute(gemm_tc_kernel,
                         cudaFuncAttributeMaxDynamicSharedMemorySize, GEMM_SMEM);
    cudaFuncSetAttribute(flash_kernel,
                         cudaFuncAttributeMaxDynamicSharedMemorySize, FLASH_SMEM);

    rope_table2_kernel<<<(64 * Ss + 255) / 256, 256>>>(base);

    dim3 gg(Dd / 128, MROWS / 128);
    gemm_tc_kernel<<<gg, 256, GEMM_SMEM>>>(subj, wq, bq, Q, 1);
    gemm_tc_kernel<<<gg, 256, GEMM_SMEM>>>(obj,  wk, bk, K, 1);
    gemm_tc_kernel<<<gg, 256, GEMM_SMEM>>>(obj,  wv, bv, V, 0);

    flash_kernel<<<dim3(Ss / 64, Hh, Bb), 256, FLASH_SMEM>>>(Q, K, V, C);

    gemm_tc_kernel<<<gg, 256, GEMM_SMEM>>>(C, wc, bc, out, 0);
}

// round 8
// speedup vs baseline: 3.2621x; 1.4887x over previous
#include <cuda_runtime.h>
#include <cuda_bf16.h>
#include <math.h>
#include <stdint.h>

#define Bb 4
#define Ss 2048
#define Dd 2048
#define Hh 16
#define HDim 128
#define MROWS (Bb * Ss)  // 8192

// Scratch (allocation-free: device globals)
__device__ float g_Q[(size_t)Bb * Ss * Dd];
__device__ float g_K[(size_t)Bb * Ss * Dd];
__device__ float g_V[(size_t)Bb * Ss * Dd];
__device__ float g_C[(size_t)Bb * Ss * Dd];
__device__ float2 g_tab2[64 * Ss];   // [j][s] -> (cos, sin)

// ---------------------------------------------------------------------------
// helpers
// ---------------------------------------------------------------------------
__device__ __forceinline__ uint32_t smem_u32(const void* p) {
    uint32_t r;
    asm("{ .reg .u64 t; cvta.to.shared.u64 t, %1; cvt.u32.u64 %0, t; }"
        : "=r"(r) : "l"(p));
    return r;
}

#define CP_ASYNC16(smem, gptr) \
    asm volatile("cp.async.cg.shared.global [%0], [%1], 16;" \
                 :: "r"(smem), "l"(gptr) : "memory")
#define CP_COMMIT() asm volatile("cp.async.commit_group;" ::: "memory")
#define CP_WAIT(n)  asm volatile("cp.async.wait_group %0;" :: "n"(n) : "memory")

__device__ __forceinline__ uint32_t cvt_tf32(float x) {
    uint32_t r;
    asm("cvt.rna.tf32.f32 %0, %1;" : "=r"(r) : "f"(x));
    return r;
}

__device__ __forceinline__ void mma_m16n8k8(float* d, const uint32_t* a,
                                            uint32_t b0, uint32_t b1) {
    asm volatile(
        "mma.sync.aligned.m16n8k8.row.col.f32.tf32.tf32.f32 "
        "{%0,%1,%2,%3}, {%4,%5,%6,%7}, {%8,%9}, {%0,%1,%2,%3};"
        : "+f"(d[0]), "+f"(d[1]), "+f"(d[2]), "+f"(d[3])
        : "r"(a[0]), "r"(a[1]), "r"(a[2]), "r"(a[3]), "r"(b0), "r"(b1));
}

__device__ __forceinline__ void mma_bf16(float* d, const uint32_t* a,
                                         uint32_t b0, uint32_t b1) {
    asm volatile(
        "mma.sync.aligned.m16n8k16.row.col.f32.bf16.bf16.f32 "
        "{%0,%1,%2,%3}, {%4,%5,%6,%7}, {%8,%9}, {%0,%1,%2,%3};"
        : "+f"(d[0]), "+f"(d[1]), "+f"(d[2]), "+f"(d[3])
        : "r"(a[0]), "r"(a[1]), "r"(a[2]), "r"(a[3]), "r"(b0), "r"(b1));
}

// split (x,y) into packed bf16 hi pair + lo pair (x in low half)
__device__ __forceinline__ void split2(float x, float y,
                                       uint32_t& hi, uint32_t& lo) {
    __nv_bfloat162 h2 = __floats2bfloat162_rn(x, y);
    float hx = __bfloat162float(h2.x);
    float hy = __bfloat162float(h2.y);
    __nv_bfloat162 l2 = __floats2bfloat162_rn(x - hx, y - hy);
    hi = *reinterpret_cast<uint32_t*>(&h2);
    lo = *reinterpret_cast<uint32_t*>(&l2);
}

// ---------------------------------------------------------------------------
// tf32 mma.sync GEMM (unchanged from R6 — known good, 437us)
// ---------------------------------------------------------------------------
#define BKt 32
#define NKT (Dd / BKt)            // 64
#define SA_STRIDE 36
#define SB_STRIDE 136
#define SA_WORDS (128 * SA_STRIDE)
#define SB_WORDS (BKt * SB_STRIDE)
#define STAGE_WORDS (SA_WORDS + SB_WORDS)
#define GEMM_SMEM (2 * STAGE_WORDS * 4)

__global__ __launch_bounds__(256, 2) void gemm_tc_kernel(
    const float* __restrict__ A, const float* __restrict__ W,
    const float* __restrict__ bias, float* __restrict__ C, int doRope)
{
    extern __shared__ float sm[];
    const int tid = threadIdx.x;
    const int wid = tid >> 5;
    const int lane = tid & 31;
    const int rowBase = blockIdx.y * 128;
    const int colBase = blockIdx.x * 128;

    const uint32_t sbase = smem_u32(sm);

    const float* aG = A + (size_t)(rowBase + (tid >> 3)) * Dd + (tid & 7) * 4;
    const float* bG = W + (size_t)(tid >> 5) * Dd + colBase + (tid & 31) * 4;
    const uint32_t aS = sbase + ((tid >> 3) * SA_STRIDE + (tid & 7) * 4) * 4;
    const uint32_t bS = sbase + (SA_WORDS + (tid >> 5) * SB_STRIDE + (tid & 31) * 4) * 4;

    const int wr = wid & 3;
    const int wc = wid >> 2;
    const int m0 = wr * 32;
    const int n0 = wc * 64;
    const int lg = lane >> 2;
    const int lc = lane & 3;

    float acc[2][8][4];
    #pragma unroll
    for (int mi = 0; mi < 2; mi++)
        #pragma unroll
        for (int ni = 0; ni < 8; ni++)
            #pragma unroll
            for (int r = 0; r < 4; r++) acc[mi][ni][r] = 0.f;

    {
        #pragma unroll
        for (int i = 0; i < 4; i++) {
            CP_ASYNC16(aS + i * 32 * SA_STRIDE * 4, aG + (size_t)(32 * i) * Dd);
            CP_ASYNC16(bS + i * 8 * SB_STRIDE * 4,  bG + (size_t)(8 * i) * Dd);
        }
        CP_COMMIT();
    }

    for (int kt = 0; kt < NKT; kt++) {
        const int s = kt & 1;
        if (kt + 1 < NKT) {
            const int s2 = (kt + 1) & 1;
            const float* ag = aG + (kt + 1) * BKt;
            const float* bg = bG + (size_t)(kt + 1) * BKt * Dd;
            const uint32_t as = aS + s2 * STAGE_WORDS * 4;
            const uint32_t bs = bS + s2 * STAGE_WORDS * 4;
            #pragma unroll
            for (int i = 0; i < 4; i++) {
                CP_ASYNC16(as + i * 32 * SA_STRIDE * 4, ag + (size_t)(32 * i) * Dd);
                CP_ASYNC16(bs + i * 8 * SB_STRIDE * 4,  bg + (size_t)(8 * i) * Dd);
            }
            CP_COMMIT();
            CP_WAIT(1);
        } else {
            CP_WAIT(0);
        }
        __syncthreads();

        const float* sAp = sm + s * STAGE_WORDS;
        const float* sBp = sAp + SA_WORDS;

        #pragma unroll
        for (int ks = 0; ks < 4; ks++) {
            const int k0 = ks * 8;
            uint32_t afr[2][4];
            #pragma unroll
            for (int mi = 0; mi < 2; mi++) {
                const int r = m0 + mi * 16 + lg;
                const int c = k0 + lc;
                afr[mi][0] = cvt_tf32(sAp[r * SA_STRIDE + c]);
                afr[mi][1] = cvt_tf32(sAp[(r + 8) * SA_STRIDE + c]);
                afr[mi][2] = cvt_tf32(sAp[r * SA_STRIDE + c + 4]);
                afr[mi][3] = cvt_tf32(sAp[(r + 8) * SA_STRIDE + c + 4]);
            }
            #pragma unroll
            for (int ni = 0; ni < 8; ni++) {
                const int col = n0 + ni * 8 + lg;
                uint32_t b0 = cvt_tf32(sBp[(k0 + lc) * SB_STRIDE + col]);
                uint32_t b1 = cvt_tf32(sBp[(k0 + 4 + lc) * SB_STRIDE + col]);
                mma_m16n8k8(acc[0][ni], afr[0], b0, b1);
                mma_m16n8k8(acc[1][ni], afr[1], b0, b1);
            }
        }
        __syncthreads();
    }

    #pragma unroll
    for (int mi = 0; mi < 2; mi++) {
        const int row = rowBase + m0 + mi * 16 + lg;
        #pragma unroll
        for (int ni = 0; ni < 8; ni++) {
            const int col = colBase + n0 + ni * 8 + 2 * lc;
            const float bv0 = __ldg(bias + col);
            const float bv1 = __ldg(bias + col + 1);
            const int jn = (col & 127) >> 1;

            #pragma unroll
            for (int half = 0; half < 2; half++) {
                const int r = row + half * 8;
                float x0 = acc[mi][ni][2 * half]     + bv0;
                float x1 = acc[mi][ni][2 * half + 1] + bv1;
                if (doRope) {
                    float2 cs = g_tab2[jn * Ss + (r & (Ss - 1))];
                    float y0 = x0 * cs.x - x1 * cs.y;
                    float y1 = x0 * cs.y + x1 * cs.x;
                    x0 = y0; x1 = y1;
                }
                *(float2*)(C + (size_t)r * Dd + col) = make_float2(x0, x1);
            }
        }
    }
}

// ---------------------------------------------------------------------------
// RoPE cos/sin table (fp64 for angle accuracy), layout [j][s]
// ---------------------------------------------------------------------------
__global__ void rope_table2_kernel(const float* __restrict__ base_p)
{
    int t = blockIdx.x * blockDim.x + threadIdx.x;
    if (t >= 64 * Ss) return;
    int j = t >> 11, s = t & (Ss - 1);
    double base = (double)(*base_p);
    double f = exp(-(double)j / 64.0 * log(base));
    double ang = (double)s * f;
    double sn, cs;
    sincos(ang, &sn, &cs);
    g_tab2[t] = make_float2((float)cs, (float)sn);
}

// ---------------------------------------------------------------------------
// Flash attention v2: bf16 split (hi+lo, 3-term) tensor-core MMA.
// CTA: 64-row Q tile, 64-key tiles, 256 threads (8 warps).
// Warp w: wr=w&3 -> rows wr*16..+15; wc=w>>2 -> S-col half / O-col half.
// All smem operands stored as packed bf16 pairs (uint32), pairs along k.
// ---------------------------------------------------------------------------
// smem word offsets (uint32 units)
#define F2_QHI 0
#define F2_QLO (F2_QHI + 64 * 68)
#define F2_KHI (F2_QLO + 64 * 68)
#define F2_KLO (F2_KHI + 64 * 68)
#define F2_VHI (F2_KLO + 64 * 68)
#define F2_VLO (F2_VHI + 128 * 36)
#define F2_PHI (F2_VLO + 128 * 36)
#define F2_PLO (F2_PHI + 64 * 36)
#define F2_RM  (F2_PLO + 64 * 36)
#define F2_RS  (F2_RM + 128)
#define F2_WORDS (F2_RS + 128)
#define FLASH2_SMEM (F2_WORDS * 4)   // 125952 B

__global__ __launch_bounds__(256, 1) void flash2_kernel(
    const float* __restrict__ Q, const float* __restrict__ K,
    const float* __restrict__ V, float* __restrict__ O)
{
    extern __shared__ uint32_t smw[];
    float* sRedM = (float*)(smw + F2_RM);
    float* sRedS = (float*)(smw + F2_RS);

    const int qt = (Ss / 64 - 1) - blockIdx.x;   // big CTAs first
    const int h = blockIdx.y, b = blockIdx.z;
    const int tid = threadIdx.x;
    const int w = tid >> 5, lane = tid & 31;
    const int lg = lane >> 2, lc = lane & 3;
    const int wr = w & 3, wc = w >> 2;
    const int m0 = wr * 16;
    const int q0 = qt * 64;
    const float scale = 0.08838834764831845f;   // 1/sqrt(128), folded into Q

    const int rA = m0 + lg;        // local row of c0,c1
    const int rB = m0 + lg + 8;    // local row of c2,c3

    // --- load Q tile (64x128), scale + split to bf16 hi/lo pairs ---
    {
        const int row = tid >> 2;
        const float* qg = Q + (size_t)(b * Ss + q0 + row) * Dd + h * HDim;
        #pragma unroll
        for (int i = 0; i < 8; i++) {
            const int c4 = (tid & 3) + 4 * i;       // float4 index 0..31
            float4 v = *(const float4*)(qg + c4 * 4);
            v.x *= scale; v.y *= scale; v.z *= scale; v.w *= scale;
            uint32_t h0, l0, h1, l1;
            split2(v.x, v.y, h0, l0);
            split2(v.z, v.w, h1, l1);
            const int dp = c4 * 2;
            smw[F2_QHI + row * 68 + dp]     = h0;
            smw[F2_QHI + row * 68 + dp + 1] = h1;
            smw[F2_QLO + row * 68 + dp]     = l0;
            smw[F2_QLO + row * 68 + dp + 1] = l1;
        }
    }

    float mrow[2] = {-1e30f, -1e30f};
    float lrow[2] = {0.f, 0.f};
    float ofr[8][4];
    #pragma unroll
    for (int n = 0; n < 8; n++)
        #pragma unroll
        for (int r = 0; r < 4; r++) ofr[n][r] = 0.f;

    for (int kt = 0; kt <= qt; kt++) {
        __syncthreads();   // prev PV done (sV) / Q-store done (first iter)

        // --- load K tile, split hi/lo ---
        {
            const int row = tid >> 2;
            const float* kg = K + (size_t)(b * Ss + kt * 64 + row) * Dd + h * HDim;
            #pragma unroll
            for (int i = 0; i < 8; i++) {
                const int c4 = (tid & 3) + 4 * i;
                float4 v = *(const float4*)(kg + c4 * 4);
                uint32_t h0, l0, h1, l1;
                split2(v.x, v.y, h0, l0);
                split2(v.z, v.w, h1, l1);
                const int dp = c4 * 2;
                smw[F2_KHI + row * 68 + dp]     = h0;
                smw[F2_KHI + row * 68 + dp + 1] = h1;
                smw[F2_KLO + row * 68 + dp]     = l0;
                smw[F2_KLO + row * 68 + dp + 1] = l1;
            }
        }
        // --- load V tile transposed: sV[d][t-pair], pairs along t ---
        {
            const int d2 = tid & 63;
            const int tp4 = tid >> 6;
            const float* vg = V + (size_t)(b * Ss + kt * 64) * Dd + h * HDim;
            #pragma unroll
            for (int i = 0; i < 8; i++) {
                const int tp = i * 4 + tp4;     // 0..31
                float2 a = *(const float2*)(vg + (size_t)(2 * tp) * Dd + 2 * d2);
                float2 c = *(const float2*)(vg + (size_t)(2 * tp + 1) * Dd + 2 * d2);
                uint32_t h0, l0, h1, l1;
                split2(a.x, c.x, h0, l0);       // d = 2*d2
                split2(a.y, c.y, h1, l1);       // d = 2*d2+1
                smw[F2_VHI + (2 * d2) * 36 + tp]     = h0;
                smw[F2_VHI + (2 * d2 + 1) * 36 + tp] = h1;
                smw[F2_VLO + (2 * d2) * 36 + tp]     = l0;
                smw[F2_VLO + (2 * d2 + 1) * 36 + tp] = l1;
            }
        }
        __syncthreads();

        // --- S = Q @ K^T (3-term bf16) : warp covers rows m0..+15, cols wc*32..+31
        float sfr[4][4];
        #pragma unroll
        for (int n = 0; n < 4; n++)
            #pragma unroll
            for (int r = 0; r < 4; r++) sfr[n][r] = 0.f;

        #pragma unroll
        for (int ks = 0; ks < 8; ks++) {
            const int kp = ks * 8;             // word (pair) offset; k0 = ks*16
            uint32_t ah[4], al[4];
            ah[0] = smw[F2_QHI + rA * 68 + kp + lc];
            ah[1] = smw[F2_QHI + rB * 68 + kp + lc];
            ah[2] = smw[F2_QHI + rA * 68 + kp + lc + 4];
            ah[3] = smw[F2_QHI + rB * 68 + kp + lc + 4];
            al[0] = smw[F2_QLO + rA * 68 + kp + lc];
            al[1] = smw[F2_QLO + rB * 68 + kp + lc];
            al[2] = smw[F2_QLO + rA * 68 + kp + lc + 4];
            al[3] = smw[F2_QLO + rB * 68 + kp + lc + 4];
            #pragma unroll
            for (int ni = 0; ni < 4; ni++) {
                const int j = wc * 32 + ni * 8 + lg;
                uint32_t bh0 = smw[F2_KHI + j * 68 + kp + lc];
                uint32_t bh1 = smw[F2_KHI + j * 68 + kp + lc + 4];
                uint32_t bl0 = smw[F2_KLO + j * 68 + kp + lc];
                uint32_t bl1 = smw[F2_KLO + j * 68 + kp + lc + 4];
                mma_bf16(sfr[ni], ah, bh0, bh1);
                mma_bf16(sfr[ni], ah, bl0, bl1);
                mma_bf16(sfr[ni], al, bh0, bh1);
            }
        }

        // --- online softmax on C-fragments ---
        const bool diag = (kt == qt);
        float vA = -1e30f, vB = -1e30f;
        #pragma unroll
        for (int ni = 0; ni < 4; ni++) {
            const int c0g = wc * 32 + ni * 8 + 2 * lc;   // local col
            if (diag) {
                if (c0g > rA)     sfr[ni][0] = -1e30f;
                if (c0g + 1 > rA) sfr[ni][1] = -1e30f;
                if (c0g > rB)     sfr[ni][2] = -1e30f;
                if (c0g + 1 > rB) sfr[ni][3] = -1e30f;
            }
            vA = fmaxf(vA, fmaxf(sfr[ni][0], sfr[ni][1]));
            vB = fmaxf(vB, fmaxf(sfr[ni][2], sfr[ni][3]));
        }
        vA = fmaxf(vA, __shfl_xor_sync(0xffffffffu, vA, 1));
        vA = fmaxf(vA, __shfl_xor_sync(0xffffffffu, vA, 2));
        vB = fmaxf(vB, __shfl_xor_sync(0xffffffffu, vB, 1));
        vB = fmaxf(vB, __shfl_xor_sync(0xffffffffu, vB, 2));
        if (lc == 0) {
            sRedM[wc * 64 + rA] = vA;
            sRedM[wc * 64 + rB] = vB;
        }
        __syncthreads();
        const float mtA = fmaxf(sRedM[rA], sRedM[64 + rA]);
        const float mtB = fmaxf(sRedM[rB], sRedM[64 + rB]);
        const float mnA = fmaxf(mrow[0], mtA);
        const float mnB = fmaxf(mrow[1], mtB);
        const float alA = __expf(mrow[0] - mnA);
        const float alB = __expf(mrow[1] - mnB);

        float sumA = 0.f, sumB = 0.f;
        #pragma unroll
        for (int ni = 0; ni < 4; ni++) {
            float p0 = __expf(sfr[ni][0] - mnA);
            float p1 = __expf(sfr[ni][1] - mnA);
            float p2 = __expf(sfr[ni][2] - mnB);
            float p3 = __expf(sfr[ni][3] - mnB);
            sumA += p0 + p1;
            sumB += p2 + p3;
            uint32_t hi, lo;
            const int colp = wc * 16 + ni * 4 + lc;
            split2(p0, p1, hi, lo);
            smw[F2_PHI + rA * 36 + colp] = hi;
            smw[F2_PLO + rA * 36 + colp] = lo;
            split2(p2, p3, hi, lo);
            smw[F2_PHI + rB * 36 + colp] = hi;
            smw[F2_PLO + rB * 36 + colp] = lo;
        }
        sumA += __shfl_xor_sync(0xffffffffu, sumA, 1);
        sumA += __shfl_xor_sync(0xffffffffu, sumA, 2);
        sumB += __shfl_xor_sync(0xffffffffu, sumB, 1);
        sumB += __shfl_xor_sync(0xffffffffu, sumB, 2);
        if (lc == 0) {
            sRedS[wc * 64 + rA] = sumA;
            sRedS[wc * 64 + rB] = sumB;
        }
        __syncthreads();   // also publishes P
        lrow[0] = lrow[0] * alA + sRedS[rA] + sRedS[64 + rA];
        lrow[1] = lrow[1] * alB + sRedS[rB] + sRedS[64 + rB];
        mrow[0] = mnA;
        mrow[1] = mnB;
        #pragma unroll
        for (int n = 0; n < 8; n++) {
            ofr[n][0] *= alA; ofr[n][1] *= alA;
            ofr[n][2] *= alB; ofr[n][3] *= alB;
        }

        // --- O += P @ V (3-term bf16): warp covers rows m0..+15, d-cols wc*64..+63
        #pragma unroll
        for (int ks2 = 0; ks2 < 4; ks2++) {
            const int kp = ks2 * 8;            // pair offset; keys ks2*16..
            uint32_t ah[4], al[4];
            ah[0] = smw[F2_PHI + rA * 36 + kp + lc];
            ah[1] = smw[F2_PHI + rB * 36 + kp + lc];
            ah[2] = smw[F2_PHI + rA * 36 + kp + lc + 4];
            ah[3] = smw[F2_PHI + rB * 36 + kp + lc + 4];
            al[0] = smw[F2_PLO + rA * 36 + kp + lc];
            al[1] = smw[F2_PLO + rB * 36 + kp + lc];
            al[2] = smw[F2_PLO + rA * 36 + kp + lc + 4];
            al[3] = smw[F2_PLO + rB * 36 + kp + lc + 4];
            #pragma unroll
            for (int ni = 0; ni < 8; ni++) {
                const int d = wc * 64 + ni * 8 + lg;
                uint32_t bh0 = smw[F2_VHI + d * 36 + kp + lc];
                uint32_t bh1 = smw[F2_VHI + d * 36 + kp + lc + 4];
                uint32_t bl0 = smw[F2_VLO + d * 36 + kp + lc];
                uint32_t bl1 = smw[F2_VLO + d * 36 + kp + lc + 4];
                mma_bf16(ofr[ni], ah, bh0, bh1);
                mma_bf16(ofr[ni], ah, bl0, bl1);
                mma_bf16(ofr[ni], al, bh0, bh1);
            }
        }
    }

    // --- write out: O rows / l ---
    const float invA = 1.f / lrow[0];
    const float invB = 1.f / lrow[1];
    float* og = O + (size_t)(b * Ss + q0) * Dd + h * HDim;
    #pragma unroll
    for (int ni = 0; ni < 8; ni++) {
        const int col = wc * 64 + ni * 8 + 2 * lc;
        *(float2*)(og + (size_t)rA * Dd + col) =
            make_float2(ofr[ni][0] * invA, ofr[ni][1] * invA);
        *(float2*)(og + (size_t)rB * Dd + col) =
            make_float2(ofr[ni][2] * invB, ofr[ni][3] * invB);
    }
}

// ---------------------------------------------------------------------------
extern "C" void kernel_launch(void* const* d_in, const int* in_sizes, int n_in,
                              void* d_out, int out_size)
{
    const float* subj = (const float*)d_in[0];
    const float* obj  = (const float*)d_in[1];
    const float* wq   = (const float*)d_in[2];
    const float* bq   = (const float*)d_in[3];
    const float* wk   = (const float*)d_in[4];
    const float* bk   = (const float*)d_in[5];
    const float* wv   = (const float*)d_in[6];
    const float* bv   = (const float*)d_in[7];
    const float* wc   = (const float*)d_in[8];
    const float* bc   = (const float*)d_in[9];
    const float* base = (const float*)d_in[10];
    float* out = (float*)d_out;

    float *Q, *K, *V, *C;
    cudaGetSymbolAddress((void**)&Q, g_Q);
    cudaGetSymbolAddress((void**)&K, g_K);
    cudaGetSymbolAddress((void**)&V, g_V);
    cudaGetSymbolAddress((void**)&C, g_C);

    cudaFuncSetAttribute(gemm_tc_kernel,
                         cudaFuncAttributeMaxDynamicSharedMemorySize, GEMM_SMEM);
    cudaFuncSetAttribute(flash2_kernel,
                         cudaFuncAttributeMaxDynamicSharedMemorySize, FLASH2_SMEM);

    rope_table2_kernel<<<(64 * Ss + 255) / 256, 256>>>(base);

    dim3 gg(Dd / 128, MROWS / 128);
    gemm_tc_kernel<<<gg, 256, GEMM_SMEM>>>(subj, wq, bq, Q, 1);
    gemm_tc_kernel<<<gg, 256, GEMM_SMEM>>>(obj,  wk, bk, K, 1);
    gemm_tc_kernel<<<gg, 256, GEMM_SMEM>>>(obj,  wv, bv, V, 0);

    flash2_kernel<<<dim3(Ss / 64, Hh, Bb), 256, FLASH2_SMEM>>>(Q, K, V, C);

    gemm_tc_kernel<<<gg, 256, GEMM_SMEM>>>(C, wc, bc, out, 0);
}

// round 9
// speedup vs baseline: 3.5990x; 1.1033x over previous
#include <cuda_runtime.h>
#include <cuda_bf16.h>
#include <math.h>
#include <stdint.h>

#define Bb 4
#define Ss 2048
#define Dd 2048
#define Hh 16
#define HDim 128
#define MROWS (Bb * Ss)  // 8192

// Scratch (allocation-free: device globals)
__device__ float g_Q[(size_t)Bb * Ss * Dd];
__device__ float g_K[(size_t)Bb * Ss * Dd];
__device__ float g_V[(size_t)Bb * Ss * Dd];
__device__ float g_C[(size_t)Bb * Ss * Dd];
__device__ float g_As[(size_t)MROWS * Dd];      // subj rounded to tf32
__device__ float g_Ao[(size_t)MROWS * Dd];      // obj rounded to tf32
__device__ float g_Wr[4][(size_t)Dd * Dd];      // weights rounded to tf32
__device__ float2 g_tab2[64 * Ss];              // [j][s] -> (cos, sin)

// ---------------------------------------------------------------------------
// helpers
// ---------------------------------------------------------------------------
__device__ __forceinline__ uint32_t smem_u32(const void* p) {
    uint32_t r;
    asm("{ .reg .u64 t; cvta.to.shared.u64 t, %1; cvt.u32.u64 %0, t; }"
        : "=r"(r) : "l"(p));
    return r;
}

#define CP_ASYNC16(smem, gptr) \
    asm volatile("cp.async.cg.shared.global [%0], [%1], 16;" \
                 :: "r"(smem), "l"(gptr) : "memory")
#define CP_COMMIT() asm volatile("cp.async.commit_group;" ::: "memory")
#define CP_WAIT(n)  asm volatile("cp.async.wait_group %0;" :: "n"(n) : "memory")

__device__ __forceinline__ uint32_t cvt_tf32(float x) {
    uint32_t r;
    asm("cvt.rna.tf32.f32 %0, %1;" : "=r"(r) : "f"(x));
    return r;
}

__device__ __forceinline__ void mma_m16n8k8(float* d, const uint32_t* a,
                                            uint32_t b0, uint32_t b1) {
    asm volatile(
        "mma.sync.aligned.m16n8k8.row.col.f32.tf32.tf32.f32 "
        "{%0,%1,%2,%3}, {%4,%5,%6,%7}, {%8,%9}, {%0,%1,%2,%3};"
        : "+f"(d[0]), "+f"(d[1]), "+f"(d[2]), "+f"(d[3])
        : "r"(a[0]), "r"(a[1]), "r"(a[2]), "r"(a[3]), "r"(b0), "r"(b1));
}

__device__ __forceinline__ void mma_bf16(float* d, const uint32_t* a,
                                         uint32_t b0, uint32_t b1) {
    asm volatile(
        "mma.sync.aligned.m16n8k16.row.col.f32.bf16.bf16.f32 "
        "{%0,%1,%2,%3}, {%4,%5,%6,%7}, {%8,%9}, {%0,%1,%2,%3};"
        : "+f"(d[0]), "+f"(d[1]), "+f"(d[2]), "+f"(d[3])
        : "r"(a[0]), "r"(a[1]), "r"(a[2]), "r"(a[3]), "r"(b0), "r"(b1));
}

// split (x,y) into packed bf16 hi pair + lo pair (x in low half)
__device__ __forceinline__ void split2(float x, float y,
                                       uint32_t& hi, uint32_t& lo) {
    __nv_bfloat162 h2 = __floats2bfloat162_rn(x, y);
    float hx = __bfloat162float(h2.x);
    float hy = __bfloat162float(h2.y);
    __nv_bfloat162 l2 = __floats2bfloat162_rn(x - hx, y - hy);
    hi = *reinterpret_cast<uint32_t*>(&h2);
    lo = *reinterpret_cast<uint32_t*>(&l2);
}

// ---------------------------------------------------------------------------
// Pre-round fp32 -> tf32-exact fp32 (RNA). n multiple of 4.
// ---------------------------------------------------------------------------
__global__ __launch_bounds__(256) void round_tf32_kernel(
    const float* __restrict__ src, float* __restrict__ dst, int n4)
{
    int i = blockIdx.x * blockDim.x + threadIdx.x;
    if (i >= n4) return;
    float4 v = ((const float4*)src)[i];
    uint4 o;
    o.x = cvt_tf32(v.x);
    o.y = cvt_tf32(v.y);
    o.z = cvt_tf32(v.z);
    o.w = cvt_tf32(v.w);
    ((uint4*)dst)[i] = o;
}

// ---------------------------------------------------------------------------
// tf32 mma.sync GEMM on PRE-ROUNDED A and W (no in-loop cvt).
// C[8192,2048] = A @ W + bias; optional fused RoPE.
// BM=BN=128, BK=32, 2-stage cp.async, 256 threads, 2 CTAs/SM.
// ---------------------------------------------------------------------------
#define BKt 32
#define NKT (Dd / BKt)            // 64
#define SA_STRIDE 36
#define SB_STRIDE 136
#define SA_WORDS (128 * SA_STRIDE)
#define SB_WORDS (BKt * SB_STRIDE)
#define STAGE_WORDS (SA_WORDS + SB_WORDS)
#define GEMM_SMEM (2 * STAGE_WORDS * 4)

__global__ __launch_bounds__(256, 2) void gemm_tc_kernel(
    const float* __restrict__ A, const float* __restrict__ W,
    const float* __restrict__ bias, float* __restrict__ C, int doRope)
{
    extern __shared__ float sm[];
    const int tid = threadIdx.x;
    const int wid = tid >> 5;
    const int lane = tid & 31;
    const int rowBase = blockIdx.y * 128;
    const int colBase = blockIdx.x * 128;

    const uint32_t sbase = smem_u32(sm);

    const float* aG = A + (size_t)(rowBase + (tid >> 3)) * Dd + (tid & 7) * 4;
    const float* bG = W + (size_t)(tid >> 5) * Dd + colBase + (tid & 31) * 4;
    const uint32_t aS = sbase + ((tid >> 3) * SA_STRIDE + (tid & 7) * 4) * 4;
    const uint32_t bS = sbase + (SA_WORDS + (tid >> 5) * SB_STRIDE + (tid & 31) * 4) * 4;

    const int wr = wid & 3;
    const int wc = wid >> 2;
    const int m0 = wr * 32;
    const int n0 = wc * 64;
    const int lg = lane >> 2;
    const int lc = lane & 3;

    float acc[2][8][4];
    #pragma unroll
    for (int mi = 0; mi < 2; mi++)
        #pragma unroll
        for (int ni = 0; ni < 8; ni++)
            #pragma unroll
            for (int r = 0; r < 4; r++) acc[mi][ni][r] = 0.f;

    {
        #pragma unroll
        for (int i = 0; i < 4; i++) {
            CP_ASYNC16(aS + i * 32 * SA_STRIDE * 4, aG + (size_t)(32 * i) * Dd);
            CP_ASYNC16(bS + i * 8 * SB_STRIDE * 4,  bG + (size_t)(8 * i) * Dd);
        }
        CP_COMMIT();
    }

    for (int kt = 0; kt < NKT; kt++) {
        const int s = kt & 1;
        if (kt + 1 < NKT) {
            const int s2 = (kt + 1) & 1;
            const float* ag = aG + (kt + 1) * BKt;
            const float* bg = bG + (size_t)(kt + 1) * BKt * Dd;
            const uint32_t as = aS + s2 * STAGE_WORDS * 4;
            const uint32_t bs = bS + s2 * STAGE_WORDS * 4;
            #pragma unroll
            for (int i = 0; i < 4; i++) {
                CP_ASYNC16(as + i * 32 * SA_STRIDE * 4, ag + (size_t)(32 * i) * Dd);
                CP_ASYNC16(bs + i * 8 * SB_STRIDE * 4,  bg + (size_t)(8 * i) * Dd);
            }
            CP_COMMIT();
            CP_WAIT(1);
        } else {
            CP_WAIT(0);
        }
        __syncthreads();

        const uint32_t* sAp = (const uint32_t*)(sm + s * STAGE_WORDS);
        const uint32_t* sBp = sAp + SA_WORDS;

        #pragma unroll
        for (int ks = 0; ks < 4; ks++) {
            const int k0 = ks * 8;
            uint32_t afr[2][4];
            #pragma unroll
            for (int mi = 0; mi < 2; mi++) {
                const int r = m0 + mi * 16 + lg;
                const int c = k0 + lc;
                afr[mi][0] = sAp[r * SA_STRIDE + c];
                afr[mi][1] = sAp[(r + 8) * SA_STRIDE + c];
                afr[mi][2] = sAp[r * SA_STRIDE + c + 4];
                afr[mi][3] = sAp[(r + 8) * SA_STRIDE + c + 4];
            }
            #pragma unroll
            for (int ni = 0; ni < 8; ni++) {
                const int col = n0 + ni * 8 + lg;
                uint32_t b0 = sBp[(k0 + lc) * SB_STRIDE + col];
                uint32_t b1 = sBp[(k0 + 4 + lc) * SB_STRIDE + col];
                mma_m16n8k8(acc[0][ni], afr[0], b0, b1);
                mma_m16n8k8(acc[1][ni], afr[1], b0, b1);
            }
        }
        __syncthreads();
    }

    #pragma unroll
    for (int mi = 0; mi < 2; mi++) {
        const int row = rowBase + m0 + mi * 16 + lg;
        #pragma unroll
        for (int ni = 0; ni < 8; ni++) {
            const int col = colBase + n0 + ni * 8 + 2 * lc;
            const float bv0 = __ldg(bias + col);
            const float bv1 = __ldg(bias + col + 1);
            const int jn = (col & 127) >> 1;

            #pragma unroll
            for (int half = 0; half < 2; half++) {
                const int r = row + half * 8;
                float x0 = acc[mi][ni][2 * half]     + bv0;
                float x1 = acc[mi][ni][2 * half + 1] + bv1;
                if (doRope) {
                    float2 cs = g_tab2[jn * Ss + (r & (Ss - 1))];
                    float y0 = x0 * cs.x - x1 * cs.y;
                    float y1 = x0 * cs.y + x1 * cs.x;
                    x0 = y0; x1 = y1;
                }
                *(float2*)(C + (size_t)r * Dd + col) = make_float2(x0, x1);
            }
        }
    }
}

// ---------------------------------------------------------------------------
// RoPE cos/sin table (fp64 for angle accuracy), layout [j][s]
// ---------------------------------------------------------------------------
__global__ void rope_table2_kernel(const float* __restrict__ base_p)
{
    int t = blockIdx.x * blockDim.x + threadIdx.x;
    if (t >= 64 * Ss) return;
    int j = t >> 11, s = t & (Ss - 1);
    double base = (double)(*base_p);
    double f = exp(-(double)j / 64.0 * log(base));
    double ang = (double)s * f;
    double sn, cs;
    sincos(ang, &sn, &cs);
    g_tab2[t] = make_float2((float)cs, (float)sn);
}

// ---------------------------------------------------------------------------
// Flash attention v3: bf16 split (hi+lo, 3-term) MMA.
// CTA: 128-row Q tile, 512 threads (16 warps), 64-key tiles.
// Warp w: wr=w&7 -> rows wr*16..+15; wc=w>>3 -> S-col half / O-col half.
// Output written tf32-pre-rounded (feeds final GEMM without cvt).
// ---------------------------------------------------------------------------
#define F3_QHI 0
#define F3_QLO (F3_QHI + 128 * 68)
#define F3_KHI (F3_QLO + 128 * 68)
#define F3_KLO (F3_KHI + 64 * 68)
#define F3_VHI (F3_KLO + 64 * 68)
#define F3_VLO (F3_VHI + 128 * 36)
#define F3_PHI (F3_VLO + 128 * 36)
#define F3_PLO (F3_PHI + 128 * 36)
#define F3_RM  (F3_PLO + 128 * 36)
#define F3_RS  (F3_RM + 256)
#define F3_WORDS (F3_RS + 256)
#define FLASH3_SMEM (F3_WORDS * 4)   // 180224 B

__global__ __launch_bounds__(512, 1) void flash3_kernel(
    const float* __restrict__ Q, const float* __restrict__ K,
    const float* __restrict__ V, float* __restrict__ O)
{
    extern __shared__ uint32_t smw[];
    float* sRedM = (float*)(smw + F3_RM);
    float* sRedS = (float*)(smw + F3_RS);

    const int qt = (Ss / 128 - 1) - blockIdx.x;   // big CTAs first
    const int h = blockIdx.y, b = blockIdx.z;
    const int tid = threadIdx.x;
    const int w = tid >> 5, lane = tid & 31;
    const int lg = lane >> 2, lc = lane & 3;
    const int wr = w & 7, wc = w >> 3;
    const int m0 = wr * 16;
    const int q0 = qt * 128;
    const float scale = 0.08838834764831845f;   // 1/sqrt(128), folded into Q

    const int rA = m0 + lg;        // local row of c0,c1
    const int rB = m0 + lg + 8;    // local row of c2,c3
    const int gRA = q0 + rA;
    const int gRB = q0 + rB;

    // --- load Q tile (128x128), scale + split to bf16 hi/lo pairs ---
    {
        const int row = tid >> 2;
        const float* qg = Q + (size_t)(b * Ss + q0 + row) * Dd + h * HDim;
        #pragma unroll
        for (int i = 0; i < 8; i++) {
            const int c4 = (tid & 3) + 4 * i;       // float4 index 0..31
            float4 v = *(const float4*)(qg + c4 * 4);
            v.x *= scale; v.y *= scale; v.z *= scale; v.w *= scale;
            uint32_t h0, l0, h1, l1;
            split2(v.x, v.y, h0, l0);
            split2(v.z, v.w, h1, l1);
            const int dp = c4 * 2;
            smw[F3_QHI + row * 68 + dp]     = h0;
            smw[F3_QHI + row * 68 + dp + 1] = h1;
            smw[F3_QLO + row * 68 + dp]     = l0;
            smw[F3_QLO + row * 68 + dp + 1] = l1;
        }
    }

    float mrow[2] = {-1e30f, -1e30f};
    float lrow[2] = {0.f, 0.f};
    float ofr[8][4];
    #pragma unroll
    for (int n = 0; n < 8; n++)
        #pragma unroll
        for (int r = 0; r < 4; r++) ofr[n][r] = 0.f;

    const int ktEnd = 2 * qt + 1;
    for (int kt = 0; kt <= ktEnd; kt++) {
        __syncthreads();   // prev PV done (sV/sP) / Q-store done (first iter)

        // --- load K tile (64x128), split hi/lo ---
        {
            const int row = tid >> 3;                // 0..63
            const float* kg = K + (size_t)(b * Ss + kt * 64 + row) * Dd + h * HDim;
            #pragma unroll
            for (int i = 0; i < 4; i++) {
                const int c4 = (tid & 7) + 8 * i;    // 0..31
                float4 v = *(const float4*)(kg + c4 * 4);
                uint32_t h0, l0, h1, l1;
                split2(v.x, v.y, h0, l0);
                split2(v.z, v.w, h1, l1);
                const int dp = c4 * 2;
                smw[F3_KHI + row * 68 + dp]     = h0;
                smw[F3_KHI + row * 68 + dp + 1] = h1;
                smw[F3_KLO + row * 68 + dp]     = l0;
                smw[F3_KLO + row * 68 + dp + 1] = l1;
            }
        }
        // --- load V tile transposed: sV[d][t-pair], pairs along t ---
        {
            const int d2 = tid & 63;
            const int tp8 = tid >> 6;                // 0..7
            const float* vg = V + (size_t)(b * Ss + kt * 64) * Dd + h * HDim;
            #pragma unroll
            for (int i = 0; i < 4; i++) {
                const int tp = i * 8 + tp8;          // 0..31
                float2 a = *(const float2*)(vg + (size_t)(2 * tp) * Dd + 2 * d2);
                float2 c = *(const float2*)(vg + (size_t)(2 * tp + 1) * Dd + 2 * d2);
                uint32_t h0, l0, h1, l1;
                split2(a.x, c.x, h0, l0);            // d = 2*d2
                split2(a.y, c.y, h1, l1);            // d = 2*d2+1
                smw[F3_VHI + (2 * d2) * 36 + tp]     = h0;
                smw[F3_VHI + (2 * d2 + 1) * 36 + tp] = h1;
                smw[F3_VLO + (2 * d2) * 36 + tp]     = l0;
                smw[F3_VLO + (2 * d2 + 1) * 36 + tp] = l1;
            }
        }
        __syncthreads();

        // --- S = Q @ K^T (3-term bf16): rows m0..+15, cols wc*32..+31
        float sfr[4][4];
        #pragma unroll
        for (int n = 0; n < 4; n++)
            #pragma unroll
            for (int r = 0; r < 4; r++) sfr[n][r] = 0.f;

        #pragma unroll
        for (int ks = 0; ks < 8; ks++) {
            const int kp = ks * 8;
            uint32_t ah[4], al[4];
            ah[0] = smw[F3_QHI + rA * 68 + kp + lc];
            ah[1] = smw[F3_QHI + rB * 68 + kp + lc];
            ah[2] = smw[F3_QHI + rA * 68 + kp + lc + 4];
            ah[3] = smw[F3_QHI + rB * 68 + kp + lc + 4];
            al[0] = smw[F3_QLO + rA * 68 + kp + lc];
            al[1] = smw[F3_QLO + rB * 68 + kp + lc];
            al[2] = smw[F3_QLO + rA * 68 + kp + lc + 4];
            al[3] = smw[F3_QLO + rB * 68 + kp + lc + 4];
            #pragma unroll
            for (int ni = 0; ni < 4; ni++) {
                const int j = wc * 32 + ni * 8 + lg;
                uint32_t bh0 = smw[F3_KHI + j * 68 + kp + lc];
                uint32_t bh1 = smw[F3_KHI + j * 68 + kp + lc + 4];
                uint32_t bl0 = smw[F3_KLO + j * 68 + kp + lc];
                uint32_t bl1 = smw[F3_KLO + j * 68 + kp + lc + 4];
                mma_bf16(sfr[ni], ah, bh0, bh1);
                mma_bf16(sfr[ni], ah, bl0, bl1);
                mma_bf16(sfr[ni], al, bh0, bh1);
            }
        }

        // --- online softmax on C-fragments ---
        const bool diag = (kt >= 2 * qt);
        float vA = -1e30f, vB = -1e30f;
        #pragma unroll
        for (int ni = 0; ni < 4; ni++) {
            if (diag) {
                const int gc0 = kt * 64 + wc * 32 + ni * 8 + 2 * lc;
                if (gc0 > gRA)     sfr[ni][0] = -1e30f;
                if (gc0 + 1 > gRA) sfr[ni][1] = -1e30f;
                if (gc0 > gRB)     sfr[ni][2] = -1e30f;
                if (gc0 + 1 > gRB) sfr[ni][3] = -1e30f;
            }
            vA = fmaxf(vA, fmaxf(sfr[ni][0], sfr[ni][1]));
            vB = fmaxf(vB, fmaxf(sfr[ni][2], sfr[ni][3]));
        }
        vA = fmaxf(vA, __shfl_xor_sync(0xffffffffu, vA, 1));
        vA = fmaxf(vA, __shfl_xor_sync(0xffffffffu, vA, 2));
        vB = fmaxf(vB, __shfl_xor_sync(0xffffffffu, vB, 1));
        vB = fmaxf(vB, __shfl_xor_sync(0xffffffffu, vB, 2));
        if (lc == 0) {
            sRedM[wc * 128 + rA] = vA;
            sRedM[wc * 128 + rB] = vB;
        }
        __syncthreads();
        const float mtA = fmaxf(sRedM[rA], sRedM[128 + rA]);
        const float mtB = fmaxf(sRedM[rB], sRedM[128 + rB]);
        const float mnA = fmaxf(mrow[0], mtA);
        const float mnB = fmaxf(mrow[1], mtB);
        const float alA = __expf(mrow[0] - mnA);
        const float alB = __expf(mrow[1] - mnB);

        float sumA = 0.f, sumB = 0.f;
        #pragma unroll
        for (int ni = 0; ni < 4; ni++) {
            float p0 = __expf(sfr[ni][0] - mnA);
            float p1 = __expf(sfr[ni][1] - mnA);
            float p2 = __expf(sfr[ni][2] - mnB);
            float p3 = __expf(sfr[ni][3] - mnB);
            sumA += p0 + p1;
            sumB += p2 + p3;
            uint32_t hi, lo;
            const int colp = wc * 16 + ni * 4 + lc;
            split2(p0, p1, hi, lo);
            smw[F3_PHI + rA * 36 + colp] = hi;
            smw[F3_PLO + rA * 36 + colp] = lo;
            split2(p2, p3, hi, lo);
            smw[F3_PHI + rB * 36 + colp] = hi;
            smw[F3_PLO + rB * 36 + colp] = lo;
        }
        sumA += __shfl_xor_sync(0xffffffffu, sumA, 1);
        sumA += __shfl_xor_sync(0xffffffffu, sumA, 2);
        sumB += __shfl_xor_sync(0xffffffffu, sumB, 1);
        sumB += __shfl_xor_sync(0xffffffffu, sumB, 2);
        if (lc == 0) {
            sRedS[wc * 128 + rA] = sumA;
            sRedS[wc * 128 + rB] = sumB;
        }
        __syncthreads();   // also publishes P
        lrow[0] = lrow[0] * alA + sRedS[rA] + sRedS[128 + rA];
        lrow[1] = lrow[1] * alB + sRedS[rB] + sRedS[128 + rB];
        mrow[0] = mnA;
        mrow[1] = mnB;
        #pragma unroll
        for (int n = 0; n < 8; n++) {
            ofr[n][0] *= alA; ofr[n][1] *= alA;
            ofr[n][2] *= alB; ofr[n][3] *= alB;
        }

        // --- O += P @ V (3-term bf16): rows m0..+15, d-cols wc*64..+63
        #pragma unroll
        for (int ks2 = 0; ks2 < 4; ks2++) {
            const int kp = ks2 * 8;
            uint32_t ah[4], al[4];
            ah[0] = smw[F3_PHI + rA * 36 + kp + lc];
            ah[1] = smw[F3_PHI + rB * 36 + kp + lc];
            ah[2] = smw[F3_PHI + rA * 36 + kp + lc + 4];
            ah[3] = smw[F3_PHI + rB * 36 + kp + lc + 4];
            al[0] = smw[F3_PLO + rA * 36 + kp + lc];
            al[1] = smw[F3_PLO + rB * 36 + kp + lc];
            al[2] = smw[F3_PLO + rA * 36 + kp + lc + 4];
            al[3] = smw[F3_PLO + rB * 36 + kp + lc + 4];
            #pragma unroll
            for (int ni = 0; ni < 8; ni++) {
                const int d = wc * 64 + ni * 8 + lg;
                uint32_t bh0 = smw[F3_VHI + d * 36 + kp + lc];
                uint32_t bh1 = smw[F3_VHI + d * 36 + kp + lc + 4];
                uint32_t bl0 = smw[F3_VLO + d * 36 + kp + lc];
                uint32_t bl1 = smw[F3_VLO + d * 36 + kp + lc + 4];
                mma_bf16(ofr[ni], ah, bh0, bh1);
                mma_bf16(ofr[ni], ah, bl0, bl1);
                mma_bf16(ofr[ni], al, bh0, bh1);
            }
        }
    }

    // --- write out (tf32-pre-rounded): O rows / l ---
    const float invA = 1.f / lrow[0];
    const float invB = 1.f / lrow[1];
    float* og = O + (size_t)(b * Ss + q0) * Dd + h * HDim;
    #pragma unroll
    for (int ni = 0; ni < 8; ni++) {
        const int col = wc * 64 + ni * 8 + 2 * lc;
        float2 oA, oB;
        oA.x = __uint_as_float(cvt_tf32(ofr[ni][0] * invA));
        oA.y = __uint_as_float(cvt_tf32(ofr[ni][1] * invA));
        oB.x = __uint_as_float(cvt_tf32(ofr[ni][2] * invB));
        oB.y = __uint_as_float(cvt_tf32(ofr[ni][3] * invB));
        *(float2*)(og + (size_t)rA * Dd + col) = oA;
        *(float2*)(og + (size_t)rB * Dd + col) = oB;
    }
}

// ---------------------------------------------------------------------------
extern "C" void kernel_launch(void* const* d_in, const int* in_sizes, int n_in,
                              void* d_out, int out_size)
{
    const float* subj = (const float*)d_in[0];
    const float* obj  = (const float*)d_in[1];
    const float* wq   = (const float*)d_in[2];
    const float* bq   = (const float*)d_in[3];
    const float* wk   = (const float*)d_in[4];
    const float* bk   = (const float*)d_in[5];
    const float* wv   = (const float*)d_in[6];
    const float* bv   = (const float*)d_in[7];
    const float* wc   = (const float*)d_in[8];
    const float* bc   = (const float*)d_in[9];
    const float* base = (const float*)d_in[10];
    float* out = (float*)d_out;

    float *Q, *K, *V, *C, *As, *Ao, *Wr;
    cudaGetSymbolAddress((void**)&Q, g_Q);
    cudaGetSymbolAddress((void**)&K, g_K);
    cudaGetSymbolAddress((void**)&V, g_V);
    cudaGetSymbolAddress((void**)&C, g_C);
    cudaGetSymbolAddress((void**)&As, g_As);
    cudaGetSymbolAddress((void**)&Ao, g_Ao);
    cudaGetSymbolAddress((void**)&Wr, g_Wr);
    const size_t WSZ = (size_t)Dd * Dd;

    cudaFuncSetAttribute(gemm_tc_kernel,
                         cudaFuncAttributeMaxDynamicSharedMemorySize, GEMM_SMEM);
    cudaFuncSetAttribute(flash3_kernel,
                         cudaFuncAttributeMaxDynamicSharedMemorySize, FLASH3_SMEM);

    rope_table2_kernel<<<(64 * Ss + 255) / 256, 256>>>(base);

    const int nA4 = (int)((size_t)MROWS * Dd / 4);
    const int nW4 = (int)(WSZ / 4);
    round_tf32_kernel<<<(nA4 + 255) / 256, 256>>>(subj, As, nA4);
    round_tf32_kernel<<<(nA4 + 255) / 256, 256>>>(obj,  Ao, nA4);
    round_tf32_kernel<<<(nW4 + 255) / 256, 256>>>(wq, Wr + 0 * WSZ, nW4);
    round_tf32_kernel<<<(nW4 + 255) / 256, 256>>>(wk, Wr + 1 * WSZ, nW4);
    round_tf32_kernel<<<(nW4 + 255) / 256, 256>>>(wv, Wr + 2 * WSZ, nW4);
    round_tf32_kernel<<<(nW4 + 255) / 256, 256>>>(wc, Wr + 3 * WSZ, nW4);

    dim3 gg(Dd / 128, MROWS / 128);
    gemm_tc_kernel<<<gg, 256, GEMM_SMEM>>>(As, Wr + 0 * WSZ, bq, Q, 1);
    gemm_tc_kernel<<<gg, 256, GEMM_SMEM>>>(Ao, Wr + 1 * WSZ, bk, K, 1);
    gemm_tc_kernel<<<gg, 256, GEMM_SMEM>>>(Ao, Wr + 2 * WSZ, bv, V, 0);

    flash3_kernel<<<dim3(Ss / 128, Hh, Bb), 512, FLASH3_SMEM>>>(Q, K, V, C);

    gemm_tc_kernel<<<gg, 256, GEMM_SMEM>>>(C, Wr + 3 * WSZ, bc, out, 0);
}